// round 1
// baseline (speedup 1.0000x reference)
#include <cuda_runtime.h>
#include <math.h>

#define D_MODEL 1024
#define NH      16
#define DK      64
#define DFF     2688
#define BATCH   2
#define SEQL    2048
#define M_ROWS  (BATCH*SEQL)   // 4096

// ---------------- scratch (device globals; no allocation APIs) ----------------
__device__ float g_xn  [(size_t)M_ROWS*D_MODEL];
__device__ float g_qkv [(size_t)M_ROWS*3*D_MODEL];
__device__ float g_attn[(size_t)M_ROWS*D_MODEL];
__device__ float g_ffa [(size_t)M_ROWS*DFF];
__device__ float g_ffb [(size_t)M_ROWS*DFF];
__device__ float g_ffh [(size_t)M_ROWS*DFF];

// ---------------- RMSNorm: one block per row, 256 threads, float4 ----------------
__global__ void rmsnorm_k(const float* __restrict__ x, const float* __restrict__ g,
                          float* __restrict__ out) {
    int row = blockIdx.x;
    const float4* x4 = (const float4*)(x + (size_t)row * D_MODEL);
    const float4* g4 = (const float4*)g;
    float4 v = x4[threadIdx.x];
    float ss = v.x*v.x + v.y*v.y + v.z*v.z + v.w*v.w;
    #pragma unroll
    for (int o = 16; o; o >>= 1) ss += __shfl_xor_sync(0xffffffffu, ss, o);
    __shared__ float wsum[8];
    int w = threadIdx.x >> 5, l = threadIdx.x & 31;
    if (l == 0) wsum[w] = ss;
    __syncthreads();
    if (w == 0) {
        float t = (l < 8) ? wsum[l] : 0.f;
        #pragma unroll
        for (int o = 4; o; o >>= 1) t += __shfl_xor_sync(0xffffffffu, t, o);
        if (l == 0) wsum[0] = t;
    }
    __syncthreads();
    float inv = rsqrtf(wsum[0] * (1.0f / (float)D_MODEL) + 1e-5f);
    float4 gg = g4[threadIdx.x];
    float4 o4 = make_float4(v.x*gg.x*inv, v.y*gg.y*inv, v.z*gg.z*inv, v.w*gg.w*inv);
    ((float4*)(out + (size_t)row * D_MODEL))[threadIdx.x] = o4;
}

// ---------------- SGEMM: C[M,N] = A[M,K] * B[N,K]^T (+ resid) ----------------
// 128x128 tile, BK=16, 256 threads, 8x8 per-thread microtile.
// All shapes here are multiples of the tile, so no bounds checks.
__global__ void __launch_bounds__(256) sgemm_k(
    const float* __restrict__ A, const float* __restrict__ B,
    const float* __restrict__ resid, float* __restrict__ C,
    int M, int N, int K)
{
    __shared__ float As[16][128];
    __shared__ float Bs[16][128];
    int tid = threadIdx.x;
    int tx = tid & 15, ty = tid >> 4;
    int m0 = blockIdx.y * 128, n0 = blockIdx.x * 128;
    int lr = tid >> 1;            // 0..127
    int lc = (tid & 1) * 8;       // 0 or 8
    const float* Ap = A + (size_t)(m0 + lr) * K + lc;
    const float* Bp = B + (size_t)(n0 + lr) * K + lc;

    float acc[8][8];
    #pragma unroll
    for (int i = 0; i < 8; i++)
        #pragma unroll
        for (int j = 0; j < 8; j++) acc[i][j] = 0.f;

    for (int kb = 0; kb < K; kb += 16) {
        float4 a0 = *(const float4*)(Ap + kb);
        float4 a1 = *(const float4*)(Ap + kb + 4);
        float4 b0 = *(const float4*)(Bp + kb);
        float4 b1 = *(const float4*)(Bp + kb + 4);
        __syncthreads();
        As[lc+0][lr] = a0.x; As[lc+1][lr] = a0.y; As[lc+2][lr] = a0.z; As[lc+3][lr] = a0.w;
        As[lc+4][lr] = a1.x; As[lc+5][lr] = a1.y; As[lc+6][lr] = a1.z; As[lc+7][lr] = a1.w;
        Bs[lc+0][lr] = b0.x; Bs[lc+1][lr] = b0.y; Bs[lc+2][lr] = b0.z; Bs[lc+3][lr] = b0.w;
        Bs[lc+4][lr] = b1.x; Bs[lc+5][lr] = b1.y; Bs[lc+6][lr] = b1.z; Bs[lc+7][lr] = b1.w;
        __syncthreads();
        #pragma unroll
        for (int kk = 0; kk < 16; kk++) {
            float4 av0 = *(const float4*)&As[kk][ty*8];
            float4 av1 = *(const float4*)&As[kk][ty*8+4];
            float4 bv0 = *(const float4*)&Bs[kk][tx*8];
            float4 bv1 = *(const float4*)&Bs[kk][tx*8+4];
            float a[8] = {av0.x,av0.y,av0.z,av0.w, av1.x,av1.y,av1.z,av1.w};
            float b[8] = {bv0.x,bv0.y,bv0.z,bv0.w, bv1.x,bv1.y,bv1.z,bv1.w};
            #pragma unroll
            for (int i = 0; i < 8; i++)
                #pragma unroll
                for (int j = 0; j < 8; j++) acc[i][j] += a[i]*b[j];
        }
    }

    #pragma unroll
    for (int i = 0; i < 8; i++) {
        int m = m0 + ty*8 + i;
        size_t off = (size_t)m * N + n0 + tx*8;
        float4 r0 = make_float4(0,0,0,0), r1 = make_float4(0,0,0,0);
        if (resid) { r0 = *(const float4*)(resid + off); r1 = *(const float4*)(resid + off + 4); }
        float4 c0 = make_float4(acc[i][0]+r0.x, acc[i][1]+r0.y, acc[i][2]+r0.z, acc[i][3]+r0.w);
        float4 c1 = make_float4(acc[i][4]+r1.x, acc[i][5]+r1.y, acc[i][6]+r1.z, acc[i][7]+r1.w);
        *(float4*)(C + off)     = c0;
        *(float4*)(C + off + 4) = c1;
    }
}

// ---------------- Fused causal attention (flash-style, fp32) ----------------
// grid: (SEQL/128, BATCH*NH); block: 128 threads (1 q-row per thread)
// qkv layout: [M_ROWS, 3*D_MODEL]; Q at col h*64, K at 1024+h*64, V at 2048+h*64
__global__ void __launch_bounds__(128) attn_k(const float* __restrict__ qkv,
                                              float* __restrict__ out) {
    __shared__ float Qs[64][128];   // transposed: [k][q] -> lane-consecutive reads
    __shared__ float Ks[32][64];
    __shared__ float Vs[32][64];
    int tid = threadIdx.x;
    int b = blockIdx.y >> 4;
    int h = blockIdx.y & 15;
    int q0 = blockIdx.x * 128;
    const float* base = qkv + (size_t)b * SEQL * (3*D_MODEL);

    // load Q tile (transposed in smem)
    for (int i = tid; i < 128*64; i += 128) {
        int qq = i >> 6, k = i & 63;
        Qs[k][qq] = base[(size_t)(q0 + qq) * (3*D_MODEL) + h*64 + k];
    }

    int q = q0 + tid;
    float O[64];
    #pragma unroll
    for (int d = 0; d < 64; d++) O[d] = 0.f;
    float mrow = -1e30f, lrow = 0.f;

    int ntiles = q0/32 + 4;  // covers keys [0, q0+128)
    for (int kt = 0; kt < ntiles; kt++) {
        __syncthreads();
        for (int i = tid; i < 32*64; i += 128) {
            int j = i >> 6, k = i & 63;
            size_t rb = (size_t)(kt*32 + j) * (3*D_MODEL) + h*64 + k;
            Ks[j][k] = base[rb + 1024];
            Vs[j][k] = base[rb + 2048];
        }
        __syncthreads();

        float s[32];
        #pragma unroll
        for (int j = 0; j < 32; j++) s[j] = 0.f;

        #pragma unroll
        for (int k0 = 0; k0 < 64; k0 += 16) {
            float qr[16];
            #pragma unroll
            for (int kk = 0; kk < 16; kk++) qr[kk] = Qs[k0+kk][tid];
            #pragma unroll
            for (int j = 0; j < 32; j++) {
                const float4* kp = (const float4*)&Ks[j][k0];
                float4 ka = kp[0], kb = kp[1], kc = kp[2], kd = kp[3];
                s[j] += qr[0]*ka.x + qr[1]*ka.y + qr[2]*ka.z + qr[3]*ka.w
                      + qr[4]*kb.x + qr[5]*kb.y + qr[6]*kb.z + qr[7]*kb.w
                      + qr[8]*kc.x + qr[9]*kc.y + qr[10]*kc.z + qr[11]*kc.w
                      + qr[12]*kd.x + qr[13]*kd.y + qr[14]*kd.z + qr[15]*kd.w;
            }
        }

        // causal mask + online softmax
        float tmax = -1e30f;
        #pragma unroll
        for (int j = 0; j < 32; j++) {
            int kg = kt*32 + j;
            float v = s[j] * 0.125f;          // 1/sqrt(64)
            if (kg > q) v = -1e30f;
            s[j] = v;
            tmax = fmaxf(tmax, v);
        }
        float mnew = fmaxf(mrow, tmax);
        float corr = __expf(mrow - mnew);
        float ls = 0.f;
        #pragma unroll
        for (int j = 0; j < 32; j++) { float p = __expf(s[j] - mnew); s[j] = p; ls += p; }
        lrow = lrow * corr + ls;
        mrow = mnew;
        #pragma unroll
        for (int d = 0; d < 64; d++) O[d] *= corr;
        #pragma unroll
        for (int j = 0; j < 32; j++) {
            float p = s[j];
            const float4* vp = (const float4*)&Vs[j][0];
            #pragma unroll
            for (int d4 = 0; d4 < 16; d4++) {
                float4 vv = vp[d4];
                O[d4*4+0] += p*vv.x; O[d4*4+1] += p*vv.y;
                O[d4*4+2] += p*vv.z; O[d4*4+3] += p*vv.w;
            }
        }
    }

    float inv = 1.f / lrow;
    float* op = out + (size_t)(b*SEQL + q) * D_MODEL + h*64;
    #pragma unroll
    for (int d4 = 0; d4 < 16; d4++) {
        float4 v = make_float4(O[d4*4+0]*inv, O[d4*4+1]*inv, O[d4*4+2]*inv, O[d4*4+3]*inv);
        *(float4*)(op + d4*4) = v;
    }
}

// ---------------- SwiGLU elementwise: h = a*sigmoid(a)*b (float4) ----------------
__global__ void swiglu_k(const float* __restrict__ a, const float* __restrict__ b,
                         float* __restrict__ h, int n4) {
    int i = blockIdx.x * blockDim.x + threadIdx.x;
    if (i < n4) {
        float4 av = ((const float4*)a)[i];
        float4 bv = ((const float4*)b)[i];
        float4 r;
        r.x = av.x * (1.f/(1.f+__expf(-av.x))) * bv.x;
        r.y = av.y * (1.f/(1.f+__expf(-av.y))) * bv.y;
        r.z = av.z * (1.f/(1.f+__expf(-av.z))) * bv.z;
        r.w = av.w * (1.f/(1.f+__expf(-av.w))) * bv.w;
        ((float4*)h)[i] = r;
    }
}

// ---------------- launch ----------------
extern "C" void kernel_launch(void* const* d_in, const int* in_sizes, int n_in,
                              void* d_out, int out_size) {
    const float* x    = (const float*)d_in[0];
    const float* wqkv = (const float*)d_in[1];
    const float* wo   = (const float*)d_in[2];
    const float* g1   = (const float*)d_in[3];
    const float* g2   = (const float*)d_in[4];
    const float* w1   = (const float*)d_in[5];
    const float* w2   = (const float*)d_in[6];
    const float* w3   = (const float*)d_in[7];
    float* out = (float*)d_out;

    float *xn, *qkv, *attn, *ffa, *ffb, *ffh;
    cudaGetSymbolAddress((void**)&xn,   g_xn);
    cudaGetSymbolAddress((void**)&qkv,  g_qkv);
    cudaGetSymbolAddress((void**)&attn, g_attn);
    cudaGetSymbolAddress((void**)&ffa,  g_ffa);
    cudaGetSymbolAddress((void**)&ffb,  g_ffb);
    cudaGetSymbolAddress((void**)&ffh,  g_ffh);

    // x1 = x + WO * attn(Q,K,V of rmsnorm(x,g1))
    rmsnorm_k<<<M_ROWS, 256>>>(x, g1, xn);
    sgemm_k<<<dim3(3*D_MODEL/128, M_ROWS/128), 256>>>(xn, wqkv, nullptr, qkv,
                                                      M_ROWS, 3*D_MODEL, D_MODEL);
    attn_k<<<dim3(SEQL/128, BATCH*NH), 128>>>(qkv, attn);
    sgemm_k<<<dim3(D_MODEL/128, M_ROWS/128), 256>>>(attn, wo, x, out,
                                                    M_ROWS, D_MODEL, D_MODEL);

    // out += W2 * swiglu(rmsnorm(out,g2))
    rmsnorm_k<<<M_ROWS, 256>>>(out, g2, xn);
    sgemm_k<<<dim3(DFF/128, M_ROWS/128), 256>>>(xn, w1, nullptr, ffa,
                                                M_ROWS, DFF, D_MODEL);
    sgemm_k<<<dim3(DFF/128, M_ROWS/128), 256>>>(xn, w3, nullptr, ffb,
                                                M_ROWS, DFF, D_MODEL);
    int n4 = M_ROWS * DFF / 4;
    swiglu_k<<<(n4 + 255)/256, 256>>>(ffa, ffb, ffh, n4);
    sgemm_k<<<dim3(D_MODEL/128, M_ROWS/128), 256>>>(ffh, w2, out, out,
                                                    M_ROWS, D_MODEL, DFF);
}

// round 3
// speedup vs baseline: 2.2010x; 2.2010x over previous
#include <cuda_runtime.h>
#include <cuda_fp16.h>
#include <cstdint>
#include <math.h>

#define D_MODEL 1024
#define NH      16
#define DFF     2688
#define BATCH   2
#define SEQL    2048
#define M_ROWS  (BATCH*SEQL)   // 4096

// ---------------- scratch (device globals; no allocation APIs) ----------------
__device__ float  g_qkv [(size_t)M_ROWS*3*D_MODEL];
__device__ float  g_ffa [(size_t)M_ROWS*DFF];
__device__ float  g_ffb [(size_t)M_ROWS*DFF];
__device__ __half g_xnh [(size_t)M_ROWS*D_MODEL];
__device__ __half g_attnh[(size_t)M_ROWS*D_MODEL];
__device__ __half g_ffhh[(size_t)M_ROWS*DFF];

#define W_TOTAL (3*D_MODEL*D_MODEL + D_MODEL*D_MODEL + 2*DFF*D_MODEL + D_MODEL*DFF)
__device__ __half g_wh[(size_t)W_TOTAL];

// ---------------- helpers ----------------
__device__ __forceinline__ uint32_t smem_u32(const void* p) {
    uint32_t a;
    asm("{ .reg .u64 t; cvta.to.shared.u64 t, %1; cvt.u32.u64 %0, t; }" : "=r"(a) : "l"(p));
    return a;
}
__device__ __forceinline__ void cp16(uint32_t saddr, const void* g) {
    asm volatile("cp.async.cg.shared.global [%0], [%1], 16;" :: "r"(saddr), "l"(g));
}
__device__ __forceinline__ void cp_commit() {
    asm volatile("cp.async.commit_group;" ::: "memory");
}
__device__ __forceinline__ void cp_wait0() {
    asm volatile("cp.async.wait_group 0;" ::: "memory");
}
__device__ __forceinline__ void ldsm4(uint32_t* r, uint32_t saddr) {
    asm volatile("ldmatrix.sync.aligned.m8n8.x4.shared.b16 {%0,%1,%2,%3}, [%4];"
        : "=r"(r[0]), "=r"(r[1]), "=r"(r[2]), "=r"(r[3]) : "r"(saddr));
}
__device__ __forceinline__ void mma16816(float* c, const uint32_t* a, uint32_t b0, uint32_t b1) {
    asm volatile(
        "mma.sync.aligned.m16n8k16.row.col.f32.f16.f16.f32 "
        "{%0,%1,%2,%3}, {%4,%5,%6,%7}, {%8,%9}, {%0,%1,%2,%3};"
        : "+f"(c[0]), "+f"(c[1]), "+f"(c[2]), "+f"(c[3])
        : "r"(a[0]), "r"(a[1]), "r"(a[2]), "r"(a[3]), "r"(b0), "r"(b1));
}
// swizzled byte offset within a 128x32-half tile (rows of 64B, 4x16B chunks)
__device__ __forceinline__ uint32_t sw_off(int row, int chunk) {
    return (uint32_t)(row * 64 + ((chunk ^ ((row >> 1) & 3)) << 4));
}

// ---------------- HMMA GEMM: C[M,N] = A[M,K](fp16) * B[N,K](fp16)^T (+resid) ----------------
#define BM 128
#define BN 128
#define BK 32
#define TILE_B 8192  // bytes per buffer per operand

__global__ void __launch_bounds__(256) gemm_hmma(
    const __half* __restrict__ A, const __half* __restrict__ B,
    const float* __restrict__ resid, float* __restrict__ C,
    int M, int N, int K)
{
    __shared__ __align__(128) __half As[2][BM*BK];
    __shared__ __align__(128) __half Bs[2][BN*BK];

    int tid = threadIdx.x;
    int wid = tid >> 5, lane = tid & 31;
    int wm = wid & 3, wn = wid >> 2;          // 4 x 2 warp grid; warp tile 32x64
    int m0 = blockIdx.y * BM, n0 = blockIdx.x * BN;

    uint32_t as_base = smem_u32(As);
    uint32_t bs_base = smem_u32(Bs);

    // cp.async mapping: thread -> (row, 2 chunks of 16B)
    int lr = tid >> 1;
    int lc = (tid & 1) * 2;
    const char* gA = (const char*)(A + (size_t)(m0 + lr) * K) + lc * 16;
    const char* gB = (const char*)(B + (size_t)(n0 + lr) * K) + lc * 16;
    uint32_t sA0 = as_base + sw_off(lr, lc);
    uint32_t sA1 = as_base + sw_off(lr, lc + 1);
    uint32_t sB0 = bs_base + sw_off(lr, lc);
    uint32_t sB1 = bs_base + sw_off(lr, lc + 1);

    // ldmatrix per-lane row/chunk selectors
    int rowsel = ((lane >> 3) & 1) * 8 + (lane & 7);
    int chunk_hi = lane >> 4;                  // 0/1

    float acc[2][8][4];
    #pragma unroll
    for (int mt = 0; mt < 2; mt++)
        #pragma unroll
        for (int nt = 0; nt < 8; nt++)
            #pragma unroll
            for (int i = 0; i < 4; i++) acc[mt][nt][i] = 0.f;

    int iters = K / BK;

    // prologue: fill buffer 0
    {
        size_t go = 0;
        cp16(sA0, gA + go); cp16(sA1, gA + go + 16);
        cp16(sB0, gB + go); cp16(sB1, gB + go + 16);
        cp_commit();
    }
    cp_wait0();
    __syncthreads();

    int buf = 0;
    for (int kb = 0; kb < iters; kb++) {
        if (kb + 1 < iters) {
            size_t go = (size_t)(kb + 1) * (BK * 2);
            uint32_t bo = (buf ^ 1) * TILE_B;
            cp16(sA0 + bo, gA + go); cp16(sA1 + bo, gA + go + 16);
            cp16(sB0 + bo, gB + go); cp16(sB1 + bo, gB + go + 16);
            cp_commit();
        }

        uint32_t ab = as_base + buf * TILE_B;
        uint32_t bb = bs_base + buf * TILE_B;
        #pragma unroll
        for (int ks = 0; ks < 2; ks++) {
            int cb = ks * 2 + chunk_hi;
            uint32_t a[2][4];
            #pragma unroll
            for (int mt = 0; mt < 2; mt++) {
                int row = wm * 32 + mt * 16 + rowsel;
                ldsm4(a[mt], ab + sw_off(row, cb));
            }
            uint32_t b[4][4];
            #pragma unroll
            for (int p = 0; p < 4; p++) {
                int row = wn * 64 + p * 16 + rowsel;
                ldsm4(b[p], bb + sw_off(row, cb));
            }
            #pragma unroll
            for (int mt = 0; mt < 2; mt++)
                #pragma unroll
                for (int nt = 0; nt < 8; nt++) {
                    int p = nt >> 1, q = nt & 1;
                    mma16816(acc[mt][nt], a[mt], b[p][q], b[p][2 + q]);
                }
        }

        if (kb + 1 < iters) cp_wait0();
        __syncthreads();
        buf ^= 1;
    }

    // epilogue
    int r0 = lane >> 2, c0 = (lane & 3) * 2;
    #pragma unroll
    for (int mt = 0; mt < 2; mt++) {
        #pragma unroll
        for (int nt = 0; nt < 8; nt++) {
            int row = m0 + wm * 32 + mt * 16 + r0;
            int col = n0 + wn * 64 + nt * 8 + c0;
            float* cp0 = C + (size_t)row * N + col;
            float* cp1 = C + (size_t)(row + 8) * N + col;
            float2 v0 = make_float2(acc[mt][nt][0], acc[mt][nt][1]);
            float2 v1 = make_float2(acc[mt][nt][2], acc[mt][nt][3]);
            if (resid) {
                const float2 r0v = *(const float2*)(resid + (size_t)row * N + col);
                const float2 r1v = *(const float2*)(resid + (size_t)(row + 8) * N + col);
                v0.x += r0v.x; v0.y += r0v.y;
                v1.x += r1v.x; v1.y += r1v.y;
            }
            *(float2*)cp0 = v0;
            *(float2*)cp1 = v1;
        }
    }
}

// ---------------- fp32 -> fp16 convert (float4 / 4-wide) ----------------
__global__ void f2h_k(const float* __restrict__ x, __half* __restrict__ y, int n4) {
    int i = blockIdx.x * blockDim.x + threadIdx.x;
    if (i < n4) {
        float4 v = ((const float4*)x)[i];
        __half2 p0 = __floats2half2_rn(v.x, v.y);
        __half2 p1 = __floats2half2_rn(v.z, v.w);
        uint2 o = make_uint2(*(uint32_t*)&p0, *(uint32_t*)&p1);
        ((uint2*)y)[i] = o;
    }
}

// ---------------- RMSNorm -> fp16 out ----------------
__global__ void rmsnorm_k(const float* __restrict__ x, const float* __restrict__ g,
                          __half* __restrict__ out) {
    int row = blockIdx.x;
    const float4* x4 = (const float4*)(x + (size_t)row * D_MODEL);
    const float4* g4 = (const float4*)g;
    float4 v = x4[threadIdx.x];
    float ss = v.x*v.x + v.y*v.y + v.z*v.z + v.w*v.w;
    #pragma unroll
    for (int o = 16; o; o >>= 1) ss += __shfl_xor_sync(0xffffffffu, ss, o);
    __shared__ float wsum[8];
    int w = threadIdx.x >> 5, l = threadIdx.x & 31;
    if (l == 0) wsum[w] = ss;
    __syncthreads();
    if (w == 0) {
        float t = (l < 8) ? wsum[l] : 0.f;
        #pragma unroll
        for (int o = 4; o; o >>= 1) t += __shfl_xor_sync(0xffffffffu, t, o);
        if (l == 0) wsum[0] = t;
    }
    __syncthreads();
    float inv = rsqrtf(wsum[0] * (1.0f / (float)D_MODEL) + 1e-5f);
    float4 gg = g4[threadIdx.x];
    __half2 p0 = __floats2half2_rn(v.x*gg.x*inv, v.y*gg.y*inv);
    __half2 p1 = __floats2half2_rn(v.z*gg.z*inv, v.w*gg.w*inv);
    ((uint2*)(out + (size_t)row * D_MODEL))[threadIdx.x] =
        make_uint2(*(uint32_t*)&p0, *(uint32_t*)&p1);
}

// ---------------- fused causal attention (flash-style, fp32; fp16 out) ----------------
__global__ void __launch_bounds__(128) attn_k(const float* __restrict__ qkv,
                                              __half* __restrict__ out) {
    __shared__ float Qs[64][128];
    __shared__ float Ks[32][64];
    __shared__ float Vs[32][64];
    int tid = threadIdx.x;
    int b = blockIdx.y >> 4;
    int h = blockIdx.y & 15;
    int q0 = blockIdx.x * 128;
    const float* base = qkv + (size_t)b * SEQL * (3*D_MODEL);

    for (int i = tid; i < 128*64; i += 128) {
        int qq = i >> 6, k = i & 63;
        Qs[k][qq] = base[(size_t)(q0 + qq) * (3*D_MODEL) + h*64 + k];
    }

    int q = q0 + tid;
    float O[64];
    #pragma unroll
    for (int d = 0; d < 64; d++) O[d] = 0.f;
    float mrow = -1e30f, lrow = 0.f;

    int ntiles = q0/32 + 4;
    for (int kt = 0; kt < ntiles; kt++) {
        __syncthreads();
        for (int i = tid; i < 32*64; i += 128) {
            int j = i >> 6, k = i & 63;
            size_t rb = (size_t)(kt*32 + j) * (3*D_MODEL) + h*64 + k;
            Ks[j][k] = base[rb + 1024];
            Vs[j][k] = base[rb + 2048];
        }
        __syncthreads();

        float s[32];
        #pragma unroll
        for (int j = 0; j < 32; j++) s[j] = 0.f;

        #pragma unroll
        for (int k0 = 0; k0 < 64; k0 += 16) {
            float qr[16];
            #pragma unroll
            for (int kk = 0; kk < 16; kk++) qr[kk] = Qs[k0+kk][tid];
            #pragma unroll
            for (int j = 0; j < 32; j++) {
                const float4* kp = (const float4*)&Ks[j][k0];
                float4 ka = kp[0], kb = kp[1], kc = kp[2], kd = kp[3];
                s[j] += qr[0]*ka.x + qr[1]*ka.y + qr[2]*ka.z + qr[3]*ka.w
                      + qr[4]*kb.x + qr[5]*kb.y + qr[6]*kb.z + qr[7]*kb.w
                      + qr[8]*kc.x + qr[9]*kc.y + qr[10]*kc.z + qr[11]*kc.w
                      + qr[12]*kd.x + qr[13]*kd.y + qr[14]*kd.z + qr[15]*kd.w;
            }
        }

        float tmax = -1e30f;
        #pragma unroll
        for (int j = 0; j < 32; j++) {
            int kg = kt*32 + j;
            float v = s[j] * 0.125f;
            if (kg > q) v = -1e30f;
            s[j] = v;
            tmax = fmaxf(tmax, v);
        }
        float mnew = fmaxf(mrow, tmax);
        float corr = __expf(mrow - mnew);
        float ls = 0.f;
        #pragma unroll
        for (int j = 0; j < 32; j++) { float p = __expf(s[j] - mnew); s[j] = p; ls += p; }
        lrow = lrow * corr + ls;
        mrow = mnew;
        #pragma unroll
        for (int d = 0; d < 64; d++) O[d] *= corr;
        #pragma unroll
        for (int j = 0; j < 32; j++) {
            float p = s[j];
            const float4* vp = (const float4*)&Vs[j][0];
            #pragma unroll
            for (int d4 = 0; d4 < 16; d4++) {
                float4 vv = vp[d4];
                O[d4*4+0] += p*vv.x; O[d4*4+1] += p*vv.y;
                O[d4*4+2] += p*vv.z; O[d4*4+3] += p*vv.w;
            }
        }
    }

    float inv = 1.f / lrow;
    __half* op = out + (size_t)(b*SEQL + q) * D_MODEL + h*64;
    #pragma unroll
    for (int d4 = 0; d4 < 16; d4++) {
        __half2 p0 = __floats2half2_rn(O[d4*4+0]*inv, O[d4*4+1]*inv);
        __half2 p1 = __floats2half2_rn(O[d4*4+2]*inv, O[d4*4+3]*inv);
        ((uint2*)op)[d4] = make_uint2(*(uint32_t*)&p0, *(uint32_t*)&p1);
    }
}

// ---------------- SwiGLU elementwise -> fp16 out ----------------
__global__ void swiglu_k(const float* __restrict__ a, const float* __restrict__ b,
                         __half* __restrict__ h, int n4) {
    int i = blockIdx.x * blockDim.x + threadIdx.x;
    if (i < n4) {
        float4 av = ((const float4*)a)[i];
        float4 bv = ((const float4*)b)[i];
        float rx = av.x * (1.f/(1.f+__expf(-av.x))) * bv.x;
        float ry = av.y * (1.f/(1.f+__expf(-av.y))) * bv.y;
        float rz = av.z * (1.f/(1.f+__expf(-av.z))) * bv.z;
        float rw = av.w * (1.f/(1.f+__expf(-av.w))) * bv.w;
        __half2 p0 = __floats2half2_rn(rx, ry);
        __half2 p1 = __floats2half2_rn(rz, rw);
        ((uint2*)h)[i] = make_uint2(*(uint32_t*)&p0, *(uint32_t*)&p1);
    }
}

// ---------------- launch ----------------
extern "C" void kernel_launch(void* const* d_in, const int* in_sizes, int n_in,
                              void* d_out, int out_size) {
    const float* x    = (const float*)d_in[0];
    const float* wqkv = (const float*)d_in[1];
    const float* wo   = (const float*)d_in[2];
    const float* g1   = (const float*)d_in[3];
    const float* g2   = (const float*)d_in[4];
    const float* w1   = (const float*)d_in[5];
    const float* w2   = (const float*)d_in[6];
    const float* w3   = (const float*)d_in[7];
    float* out = (float*)d_out;

    float *qkv, *ffa, *ffb;
    __half *xnh, *attnh, *ffhh, *wh;
    cudaGetSymbolAddress((void**)&qkv,   g_qkv);
    cudaGetSymbolAddress((void**)&ffa,   g_ffa);
    cudaGetSymbolAddress((void**)&ffb,   g_ffb);
    cudaGetSymbolAddress((void**)&xnh,   g_xnh);
    cudaGetSymbolAddress((void**)&attnh, g_attnh);
    cudaGetSymbolAddress((void**)&ffhh,  g_ffhh);
    cudaGetSymbolAddress((void**)&wh,    g_wh);

    // weight offsets in g_wh
    size_t o_qkv = 0;
    size_t o_wo  = o_qkv + (size_t)3*D_MODEL*D_MODEL;
    size_t o_w1  = o_wo  + (size_t)D_MODEL*D_MODEL;
    size_t o_w3  = o_w1  + (size_t)DFF*D_MODEL;
    size_t o_w2  = o_w3  + (size_t)DFF*D_MODEL;

    f2h_k<<<(3*D_MODEL*D_MODEL/4 + 255)/256, 256>>>(wqkv, wh + o_qkv, 3*D_MODEL*D_MODEL/4);
    f2h_k<<<(D_MODEL*D_MODEL/4 + 255)/256, 256>>>(wo, wh + o_wo, D_MODEL*D_MODEL/4);
    f2h_k<<<(DFF*D_MODEL/4 + 255)/256, 256>>>(w1, wh + o_w1, DFF*D_MODEL/4);
    f2h_k<<<(DFF*D_MODEL/4 + 255)/256, 256>>>(w3, wh + o_w3, DFF*D_MODEL/4);
    f2h_k<<<(D_MODEL*DFF/4 + 255)/256, 256>>>(w2, wh + o_w2, D_MODEL*DFF/4);

    // x1 = x + WO * attn(Q,K,V of rmsnorm(x,g1))
    rmsnorm_k<<<M_ROWS, 256>>>(x, g1, xnh);
    gemm_hmma<<<dim3(3*D_MODEL/BN, M_ROWS/BM), 256>>>(
        xnh, wh + o_qkv, nullptr, qkv, M_ROWS, 3*D_MODEL, D_MODEL);
    attn_k<<<dim3(SEQL/128, BATCH*NH), 128>>>(qkv, attnh);
    gemm_hmma<<<dim3(D_MODEL/BN, M_ROWS/BM), 256>>>(
        attnh, wh + o_wo, x, out, M_ROWS, D_MODEL, D_MODEL);

    // out += W2 * swiglu(rmsnorm(out,g2))
    rmsnorm_k<<<M_ROWS, 256>>>(out, g2, xnh);
    gemm_hmma<<<dim3(DFF/BN, M_ROWS/BM), 256>>>(
        xnh, wh + o_w1, nullptr, ffa, M_ROWS, DFF, D_MODEL);
    gemm_hmma<<<dim3(DFF/BN, M_ROWS/BM), 256>>>(
        xnh, wh + o_w3, nullptr, ffb, M_ROWS, DFF, D_MODEL);
    int n4 = M_ROWS * DFF / 4;
    swiglu_k<<<(n4 + 255)/256, 256>>>(ffa, ffb, ffhh, n4);
    gemm_hmma<<<dim3(D_MODEL/BN, M_ROWS/BM), 256>>>(
        ffhh, wh + o_w2, out, out, M_ROWS, D_MODEL, DFF);
}

// round 4
// speedup vs baseline: 6.2411x; 2.8356x over previous
#include <cuda_runtime.h>
#include <cuda_fp16.h>
#include <cstdint>
#include <math.h>

#define D_MODEL 1024
#define NH      16
#define DFF     2688
#define BATCH   2
#define SEQL    2048
#define M_ROWS  (BATCH*SEQL)   // 4096

// ---------------- scratch (device globals; no allocation APIs) ----------------
__device__ float  g_ffa [(size_t)M_ROWS*DFF];
__device__ float  g_ffb [(size_t)M_ROWS*DFF];
__device__ __half g_xnh [(size_t)M_ROWS*D_MODEL];
__device__ __half g_qkvh[(size_t)M_ROWS*3*D_MODEL];
__device__ __half g_attnh[(size_t)M_ROWS*D_MODEL];
__device__ __half g_ffhh[(size_t)M_ROWS*DFF];

#define W_TOTAL (3*D_MODEL*D_MODEL + D_MODEL*D_MODEL + 2*DFF*D_MODEL + D_MODEL*DFF)
__device__ __half g_wh[(size_t)W_TOTAL];

// ---------------- helpers ----------------
__device__ __forceinline__ uint32_t smem_u32(const void* p) {
    uint32_t a;
    asm("{ .reg .u64 t; cvta.to.shared.u64 t, %1; cvt.u32.u64 %0, t; }" : "=r"(a) : "l"(p));
    return a;
}
__device__ __forceinline__ void cp16(uint32_t saddr, const void* g) {
    asm volatile("cp.async.cg.shared.global [%0], [%1], 16;" :: "r"(saddr), "l"(g));
}
__device__ __forceinline__ void cp_commit() {
    asm volatile("cp.async.commit_group;" ::: "memory");
}
__device__ __forceinline__ void cp_wait0() {
    asm volatile("cp.async.wait_group 0;" ::: "memory");
}
__device__ __forceinline__ void cp_wait1() {
    asm volatile("cp.async.wait_group 1;" ::: "memory");
}
__device__ __forceinline__ void ldsm4(uint32_t* r, uint32_t saddr) {
    asm volatile("ldmatrix.sync.aligned.m8n8.x4.shared.b16 {%0,%1,%2,%3}, [%4];"
        : "=r"(r[0]), "=r"(r[1]), "=r"(r[2]), "=r"(r[3]) : "r"(saddr));
}
__device__ __forceinline__ void ldsm2(uint32_t* r, uint32_t saddr) {
    asm volatile("ldmatrix.sync.aligned.m8n8.x2.shared.b16 {%0,%1}, [%2];"
        : "=r"(r[0]), "=r"(r[1]) : "r"(saddr));
}
__device__ __forceinline__ void ldsm2t(uint32_t* r, uint32_t saddr) {
    asm volatile("ldmatrix.sync.aligned.m8n8.x2.trans.shared.b16 {%0,%1}, [%2];"
        : "=r"(r[0]), "=r"(r[1]) : "r"(saddr));
}
__device__ __forceinline__ void mma16816(float* c, const uint32_t* a, uint32_t b0, uint32_t b1) {
    asm volatile(
        "mma.sync.aligned.m16n8k16.row.col.f32.f16.f16.f32 "
        "{%0,%1,%2,%3}, {%4,%5,%6,%7}, {%8,%9}, {%0,%1,%2,%3};"
        : "+f"(c[0]), "+f"(c[1]), "+f"(c[2]), "+f"(c[3])
        : "r"(a[0]), "r"(a[1]), "r"(a[2]), "r"(a[3]), "r"(b0), "r"(b1));
}
__device__ __forceinline__ uint32_t pack_h2(float a, float b) {
    __half2 h = __floats2half2_rn(a, b);
    return *(uint32_t*)&h;
}
// swizzled byte offset within a tile of 64B rows (4x16B chunks)
__device__ __forceinline__ uint32_t sw_off(int row, int chunk) {
    return (uint32_t)(row * 64 + ((chunk ^ ((row >> 1) & 3)) << 4));
}

// ---------------- HMMA GEMM: C[M,N] = A[M,K](fp16)*B[N,K](fp16)^T (+resid) ----------------
#define BM 128
#define BN 128
#define BK 32
#define TILE_B 8192

template<bool OUT_HALF>
__global__ void __launch_bounds__(256) gemm_hmma(
    const __half* __restrict__ A, const __half* __restrict__ B,
    const float* __restrict__ resid, void* __restrict__ Cv,
    int M, int N, int K)
{
    __shared__ __align__(128) __half As[2][BM*BK];
    __shared__ __align__(128) __half Bs[2][BN*BK];

    int tid = threadIdx.x;
    int wid = tid >> 5, lane = tid & 31;
    int wm = wid & 3, wn = wid >> 2;
    int m0 = blockIdx.y * BM, n0 = blockIdx.x * BN;

    uint32_t as_base = smem_u32(As);
    uint32_t bs_base = smem_u32(Bs);

    int lr = tid >> 1;
    int lc = (tid & 1) * 2;
    const char* gA = (const char*)(A + (size_t)(m0 + lr) * K) + lc * 16;
    const char* gB = (const char*)(B + (size_t)(n0 + lr) * K) + lc * 16;
    uint32_t sA0 = as_base + sw_off(lr, lc);
    uint32_t sA1 = as_base + sw_off(lr, lc + 1);
    uint32_t sB0 = bs_base + sw_off(lr, lc);
    uint32_t sB1 = bs_base + sw_off(lr, lc + 1);

    int rowsel = ((lane >> 3) & 1) * 8 + (lane & 7);
    int chunk_hi = lane >> 4;

    float acc[2][8][4];
    #pragma unroll
    for (int mt = 0; mt < 2; mt++)
        #pragma unroll
        for (int nt = 0; nt < 8; nt++)
            #pragma unroll
            for (int i = 0; i < 4; i++) acc[mt][nt][i] = 0.f;

    int iters = K / BK;
    cp16(sA0, gA); cp16(sA1, gA + 16);
    cp16(sB0, gB); cp16(sB1, gB + 16);
    cp_commit();
    cp_wait0();
    __syncthreads();

    int buf = 0;
    for (int kb = 0; kb < iters; kb++) {
        if (kb + 1 < iters) {
            size_t go = (size_t)(kb + 1) * (BK * 2);
            uint32_t bo = (buf ^ 1) * TILE_B;
            cp16(sA0 + bo, gA + go); cp16(sA1 + bo, gA + go + 16);
            cp16(sB0 + bo, gB + go); cp16(sB1 + bo, gB + go + 16);
            cp_commit();
        }
        uint32_t ab = as_base + buf * TILE_B;
        uint32_t bb = bs_base + buf * TILE_B;
        #pragma unroll
        for (int ks = 0; ks < 2; ks++) {
            int cb = ks * 2 + chunk_hi;
            uint32_t a[2][4];
            #pragma unroll
            for (int mt = 0; mt < 2; mt++) {
                int row = wm * 32 + mt * 16 + rowsel;
                ldsm4(a[mt], ab + sw_off(row, cb));
            }
            uint32_t b[4][4];
            #pragma unroll
            for (int p = 0; p < 4; p++) {
                int row = wn * 64 + p * 16 + rowsel;
                ldsm4(b[p], bb + sw_off(row, cb));
            }
            #pragma unroll
            for (int mt = 0; mt < 2; mt++)
                #pragma unroll
                for (int nt = 0; nt < 8; nt++) {
                    int p = nt >> 1, q = nt & 1;
                    mma16816(acc[mt][nt], a[mt], b[p][q], b[p][2 + q]);
                }
        }
        if (kb + 1 < iters) cp_wait0();
        __syncthreads();
        buf ^= 1;
    }

    int r0 = lane >> 2, c0 = (lane & 3) * 2;
    #pragma unroll
    for (int mt = 0; mt < 2; mt++) {
        #pragma unroll
        for (int nt = 0; nt < 8; nt++) {
            int row = m0 + wm * 32 + mt * 16 + r0;
            int col = n0 + wn * 64 + nt * 8 + c0;
            if (OUT_HALF) {
                __half* C = (__half*)Cv;
                *(uint32_t*)(C + (size_t)row * N + col)       = pack_h2(acc[mt][nt][0], acc[mt][nt][1]);
                *(uint32_t*)(C + (size_t)(row + 8) * N + col) = pack_h2(acc[mt][nt][2], acc[mt][nt][3]);
            } else {
                float* C = (float*)Cv;
                float2 v0 = make_float2(acc[mt][nt][0], acc[mt][nt][1]);
                float2 v1 = make_float2(acc[mt][nt][2], acc[mt][nt][3]);
                if (resid) {
                    float2 a0 = *(const float2*)(resid + (size_t)row * N + col);
                    float2 a1 = *(const float2*)(resid + (size_t)(row + 8) * N + col);
                    v0.x += a0.x; v0.y += a0.y; v1.x += a1.x; v1.y += a1.y;
                }
                *(float2*)(C + (size_t)row * N + col)       = v0;
                *(float2*)(C + (size_t)(row + 8) * N + col) = v1;
            }
        }
    }
}

// ---------------- HMMA flash attention (fp16 in/out, fp32 softmax) ----------------
// grid (SEQL/128, BATCH*NH), 256 threads (8 warps x 16 q-rows). KV tiles 64, double-buffered.
__global__ void __launch_bounds__(256) attn_hmma(const __half* __restrict__ qkv,
                                                 __half* __restrict__ out) {
    __shared__ __align__(128) __half Qs[128*64];
    __shared__ __align__(128) __half Ks[2][64*64];
    __shared__ __align__(128) __half Vs[2][64*64];
    const int tid = threadIdx.x, lane = tid & 31, wid = tid >> 5;
    const int b = blockIdx.y >> 4, h = blockIdx.y & 15;
    const int q0 = blockIdx.x * 128;
    const __half* base = qkv + (size_t)b * SEQL * (3*D_MODEL) + h * 64;

    uint32_t qs  = smem_u32(Qs);
    uint32_t ksm = smem_u32(Ks);
    uint32_t vsm = smem_u32(Vs);

    // Q tile load (rows of 128B, XOR-swizzled 16B chunks)
    {
        int r = tid >> 1, c0 = (tid & 1) * 4;
        const char* g = (const char*)(base + (size_t)(q0 + r) * (3*D_MODEL));
        #pragma unroll
        for (int c = 0; c < 4; c++) {
            int ch = c0 + c;
            cp16(qs + r * 128 + ((ch ^ (r & 7)) << 4), g + ch * 16);
        }
    }
    const int T = q0 / 64 + 2;

    {   // KV tile 0
        int r = tid >> 2, c0 = (tid & 3) * 2;
        const char* gk = (const char*)(base + 1024 + (size_t)r * (3*D_MODEL));
        const char* gv = (const char*)(base + 2048 + (size_t)r * (3*D_MODEL));
        #pragma unroll
        for (int c = 0; c < 2; c++) {
            int ch = c0 + c;
            uint32_t sw = r * 128 + ((ch ^ (r & 7)) << 4);
            cp16(ksm + sw, gk + ch * 16);
            cp16(vsm + sw, gv + ch * 16);
        }
    }
    cp_commit();
    cp_wait0();
    __syncthreads();

    // Q fragments: aq[ks][4] covers 16 rows x k16
    uint32_t aq[4][4];
    {
        int row = wid * 16 + (lane & 15);
        #pragma unroll
        for (int ks = 0; ks < 4; ks++) {
            int ch = 2 * ks + (lane >> 4);
            ldsm4(aq[ks], qs + row * 128 + ((ch ^ (row & 7)) << 4));
        }
    }

    float acc_o[8][4];
    #pragma unroll
    for (int j = 0; j < 8; j++)
        #pragma unroll
        for (int i = 0; i < 4; i++) acc_o[j][i] = 0.f;
    float m_lo = -1e30f, m_hi = -1e30f, l_lo = 0.f, l_hi = 0.f;

    for (int t = 0; t < T; t++) {
        int buf = t & 1;
        if (t + 1 < T) {
            int r = tid >> 2, c0 = (tid & 3) * 2;
            const char* gk = (const char*)(base + 1024 + (size_t)((t+1)*64 + r) * (3*D_MODEL));
            const char* gv = (const char*)(base + 2048 + (size_t)((t+1)*64 + r) * (3*D_MODEL));
            uint32_t so = (uint32_t)(buf ^ 1) * 8192 + r * 128;
            #pragma unroll
            for (int c = 0; c < 2; c++) {
                int ch = c0 + c;
                uint32_t sw = so + ((ch ^ (r & 7)) << 4);
                cp16(ksm + sw, gk + ch * 16);
                cp16(vsm + sw, gv + ch * 16);
            }
            cp_commit();
            cp_wait1();
        } else {
            cp_wait0();
        }
        __syncthreads();

        uint32_t kb = ksm + buf * 8192;
        uint32_t vb = vsm + buf * 8192;

        // S = Q K^T  (16q x 64kv per warp)
        float s[8][4];
        #pragma unroll
        for (int j = 0; j < 8; j++)
            #pragma unroll
            for (int i = 0; i < 4; i++) s[j][i] = 0.f;
        #pragma unroll
        for (int ks = 0; ks < 4; ks++) {
            #pragma unroll
            for (int j = 0; j < 8; j++) {
                int row = j * 8 + (lane & 7);
                int ch = 2 * ks + ((lane >> 3) & 1);
                uint32_t bk[2];
                ldsm2(bk, kb + row * 128 + ((ch ^ (row & 7)) << 4));
                mma16816(s[j], aq[ks], bk[0], bk[1]);
            }
        }

        // scale + causal mask
        bool need_mask = (t >= T - 2);
        int q_lo = q0 + wid * 16 + (lane >> 2);
        int kvb  = t * 64 + (lane & 3) * 2;
        float mx_lo = -1e30f, mx_hi = -1e30f;
        #pragma unroll
        for (int j = 0; j < 8; j++) {
            #pragma unroll
            for (int c = 0; c < 4; c++) {
                float v = s[j][c] * 0.125f;
                if (need_mask) {
                    int kv = kvb + j * 8 + (c & 1);
                    int qr = q_lo + ((c >= 2) ? 8 : 0);
                    if (kv > qr) v = -1e30f;
                }
                s[j][c] = v;
            }
            mx_lo = fmaxf(mx_lo, fmaxf(s[j][0], s[j][1]));
            mx_hi = fmaxf(mx_hi, fmaxf(s[j][2], s[j][3]));
        }
        mx_lo = fmaxf(mx_lo, __shfl_xor_sync(0xffffffffu, mx_lo, 1));
        mx_lo = fmaxf(mx_lo, __shfl_xor_sync(0xffffffffu, mx_lo, 2));
        mx_hi = fmaxf(mx_hi, __shfl_xor_sync(0xffffffffu, mx_hi, 1));
        mx_hi = fmaxf(mx_hi, __shfl_xor_sync(0xffffffffu, mx_hi, 2));

        float mn_lo = fmaxf(m_lo, mx_lo), mn_hi = fmaxf(m_hi, mx_hi);
        float cr_lo = __expf(m_lo - mn_lo), cr_hi = __expf(m_hi - mn_hi);
        m_lo = mn_lo; m_hi = mn_hi;

        float pl = 0.f, ph = 0.f;
        #pragma unroll
        for (int j = 0; j < 8; j++) {
            s[j][0] = __expf(s[j][0] - mn_lo); pl += s[j][0];
            s[j][1] = __expf(s[j][1] - mn_lo); pl += s[j][1];
            s[j][2] = __expf(s[j][2] - mn_hi); ph += s[j][2];
            s[j][3] = __expf(s[j][3] - mn_hi); ph += s[j][3];
        }
        pl += __shfl_xor_sync(0xffffffffu, pl, 1);
        pl += __shfl_xor_sync(0xffffffffu, pl, 2);
        ph += __shfl_xor_sync(0xffffffffu, ph, 1);
        ph += __shfl_xor_sync(0xffffffffu, ph, 2);
        l_lo = l_lo * cr_lo + pl;
        l_hi = l_hi * cr_hi + ph;

        #pragma unroll
        for (int j = 0; j < 8; j++) {
            acc_o[j][0] *= cr_lo; acc_o[j][1] *= cr_lo;
            acc_o[j][2] *= cr_hi; acc_o[j][3] *= cr_hi;
        }

        // repack P into A fragments (16q x 16kv per c16)
        uint32_t ap[4][4];
        #pragma unroll
        for (int c16 = 0; c16 < 4; c16++) {
            ap[c16][0] = pack_h2(s[2*c16][0],   s[2*c16][1]);
            ap[c16][1] = pack_h2(s[2*c16][2],   s[2*c16][3]);
            ap[c16][2] = pack_h2(s[2*c16+1][0], s[2*c16+1][1]);
            ap[c16][3] = pack_h2(s[2*c16+1][2], s[2*c16+1][3]);
        }

        // O += P V
        #pragma unroll
        for (int c16 = 0; c16 < 4; c16++) {
            int row = c16 * 16 + (lane & 15);
            #pragma unroll
            for (int j = 0; j < 8; j++) {
                uint32_t bv[2];
                ldsm2t(bv, vb + row * 128 + ((j ^ (row & 7)) << 4));
                mma16816(acc_o[j], ap[c16], bv[0], bv[1]);
            }
        }
        __syncthreads();
    }

    float il_lo = 1.f / l_lo, il_hi = 1.f / l_hi;
    int r = lane >> 2, c = (lane & 3) * 2;
    __half* o_lo = out + (size_t)((b*SEQL) + q0 + wid*16 + r) * D_MODEL + h * 64 + c;
    __half* o_hi = o_lo + (size_t)8 * D_MODEL;
    #pragma unroll
    for (int j = 0; j < 8; j++) {
        *(uint32_t*)(o_lo + j*8) = pack_h2(acc_o[j][0]*il_lo, acc_o[j][1]*il_lo);
        *(uint32_t*)(o_hi + j*8) = pack_h2(acc_o[j][2]*il_hi, acc_o[j][3]*il_hi);
    }
}

// ---------------- fp32 -> fp16 convert ----------------
__global__ void f2h_k(const float* __restrict__ x, __half* __restrict__ y, int n4) {
    int i = blockIdx.x * blockDim.x + threadIdx.x;
    if (i < n4) {
        float4 v = ((const float4*)x)[i];
        ((uint2*)y)[i] = make_uint2(pack_h2(v.x, v.y), pack_h2(v.z, v.w));
    }
}

// ---------------- RMSNorm -> fp16 ----------------
__global__ void rmsnorm_k(const float* __restrict__ x, const float* __restrict__ g,
                          __half* __restrict__ out) {
    int row = blockIdx.x;
    const float4* x4 = (const float4*)(x + (size_t)row * D_MODEL);
    const float4* g4 = (const float4*)g;
    float4 v = x4[threadIdx.x];
    float ss = v.x*v.x + v.y*v.y + v.z*v.z + v.w*v.w;
    #pragma unroll
    for (int o = 16; o; o >>= 1) ss += __shfl_xor_sync(0xffffffffu, ss, o);
    __shared__ float wsum[8];
    int w = threadIdx.x >> 5, l = threadIdx.x & 31;
    if (l == 0) wsum[w] = ss;
    __syncthreads();
    if (w == 0) {
        float t = (l < 8) ? wsum[l] : 0.f;
        #pragma unroll
        for (int o = 4; o; o >>= 1) t += __shfl_xor_sync(0xffffffffu, t, o);
        if (l == 0) wsum[0] = t;
    }
    __syncthreads();
    float inv = rsqrtf(wsum[0] * (1.0f / (float)D_MODEL) + 1e-5f);
    float4 gg = g4[threadIdx.x];
    ((uint2*)(out + (size_t)row * D_MODEL))[threadIdx.x] =
        make_uint2(pack_h2(v.x*gg.x*inv, v.y*gg.y*inv), pack_h2(v.z*gg.z*inv, v.w*gg.w*inv));
}

// ---------------- SwiGLU -> fp16 ----------------
__global__ void swiglu_k(const float* __restrict__ a, const float* __restrict__ b,
                         __half* __restrict__ h, int n4) {
    int i = blockIdx.x * blockDim.x + threadIdx.x;
    if (i < n4) {
        float4 av = ((const float4*)a)[i];
        float4 bv = ((const float4*)b)[i];
        float rx = av.x * (1.f/(1.f+__expf(-av.x))) * bv.x;
        float ry = av.y * (1.f/(1.f+__expf(-av.y))) * bv.y;
        float rz = av.z * (1.f/(1.f+__expf(-av.z))) * bv.z;
        float rw = av.w * (1.f/(1.f+__expf(-av.w))) * bv.w;
        ((uint2*)h)[i] = make_uint2(pack_h2(rx, ry), pack_h2(rz, rw));
    }
}

// ---------------- launch ----------------
extern "C" void kernel_launch(void* const* d_in, const int* in_sizes, int n_in,
                              void* d_out, int out_size) {
    const float* x    = (const float*)d_in[0];
    const float* wqkv = (const float*)d_in[1];
    const float* wo   = (const float*)d_in[2];
    const float* g1   = (const float*)d_in[3];
    const float* g2   = (const float*)d_in[4];
    const float* w1   = (const float*)d_in[5];
    const float* w2   = (const float*)d_in[6];
    const float* w3   = (const float*)d_in[7];
    float* out = (float*)d_out;

    float *ffa, *ffb;
    __half *xnh, *qkvh, *attnh, *ffhh, *wh;
    cudaGetSymbolAddress((void**)&ffa,   g_ffa);
    cudaGetSymbolAddress((void**)&ffb,   g_ffb);
    cudaGetSymbolAddress((void**)&xnh,   g_xnh);
    cudaGetSymbolAddress((void**)&qkvh,  g_qkvh);
    cudaGetSymbolAddress((void**)&attnh, g_attnh);
    cudaGetSymbolAddress((void**)&ffhh,  g_ffhh);
    cudaGetSymbolAddress((void**)&wh,    g_wh);

    size_t o_qkv = 0;
    size_t o_wo  = o_qkv + (size_t)3*D_MODEL*D_MODEL;
    size_t o_w1  = o_wo  + (size_t)D_MODEL*D_MODEL;
    size_t o_w3  = o_w1  + (size_t)DFF*D_MODEL;
    size_t o_w2  = o_w3  + (size_t)DFF*D_MODEL;

    f2h_k<<<(3*D_MODEL*D_MODEL/4 + 255)/256, 256>>>(wqkv, wh + o_qkv, 3*D_MODEL*D_MODEL/4);
    f2h_k<<<(D_MODEL*D_MODEL/4 + 255)/256, 256>>>(wo, wh + o_wo, D_MODEL*D_MODEL/4);
    f2h_k<<<(DFF*D_MODEL/4 + 255)/256, 256>>>(w1, wh + o_w1, DFF*D_MODEL/4);
    f2h_k<<<(DFF*D_MODEL/4 + 255)/256, 256>>>(w3, wh + o_w3, DFF*D_MODEL/4);
    f2h_k<<<(D_MODEL*DFF/4 + 255)/256, 256>>>(w2, wh + o_w2, D_MODEL*DFF/4);

    // x1 = x + WO * attn(QKV of rmsnorm(x,g1))
    rmsnorm_k<<<M_ROWS, 256>>>(x, g1, xnh);
    gemm_hmma<true><<<dim3(3*D_MODEL/BN, M_ROWS/BM), 256>>>(
        xnh, wh + o_qkv, nullptr, qkvh, M_ROWS, 3*D_MODEL, D_MODEL);
    attn_hmma<<<dim3(SEQL/128, BATCH*NH), 256>>>(qkvh, attnh);
    gemm_hmma<false><<<dim3(D_MODEL/BN, M_ROWS/BM), 256>>>(
        attnh, wh + o_wo, x, out, M_ROWS, D_MODEL, D_MODEL);

    // out += W2 * swiglu(rmsnorm(out,g2))
    rmsnorm_k<<<M_ROWS, 256>>>(out, g2, xnh);
    gemm_hmma<false><<<dim3(DFF/BN, M_ROWS/BM), 256>>>(
        xnh, wh + o_w1, nullptr, ffa, M_ROWS, DFF, D_MODEL);
    gemm_hmma<false><<<dim3(DFF/BN, M_ROWS/BM), 256>>>(
        xnh, wh + o_w3, nullptr, ffb, M_ROWS, DFF, D_MODEL);
    int n4 = M_ROWS * DFF / 4;
    swiglu_k<<<(n4 + 255)/256, 256>>>(ffa, ffb, ffhh, n4);
    gemm_hmma<false><<<dim3(D_MODEL/BN, M_ROWS/BM), 256>>>(
        ffhh, wh + o_w2, out, out, M_ROWS, D_MODEL, DFF);
}

// round 5
// speedup vs baseline: 6.2709x; 1.0048x over previous
#include <cuda_runtime.h>
#include <cuda_fp16.h>
#include <cstdint>
#include <math.h>

#define D_MODEL 1024
#define NH      16
#define DFF     2688
#define BATCH   2
#define SEQL    2048
#define M_ROWS  (BATCH*SEQL)   // 4096

// ---------------- scratch (device globals; no allocation APIs) ----------------
__device__ __half g_xnh [(size_t)M_ROWS*D_MODEL];
__device__ __half g_qkvh[(size_t)M_ROWS*3*D_MODEL];
__device__ __half g_attnh[(size_t)M_ROWS*D_MODEL];
__device__ __half g_ffhh[(size_t)M_ROWS*DFF];

#define W_TOTAL (3*D_MODEL*D_MODEL + D_MODEL*D_MODEL + 2*DFF*D_MODEL + D_MODEL*DFF)
__device__ __half g_wh[(size_t)W_TOTAL];

// ---------------- helpers ----------------
__device__ __forceinline__ uint32_t smem_u32(const void* p) {
    uint32_t a;
    asm("{ .reg .u64 t; cvta.to.shared.u64 t, %1; cvt.u32.u64 %0, t; }" : "=r"(a) : "l"(p));
    return a;
}
__device__ __forceinline__ void cp16(uint32_t saddr, const void* g) {
    asm volatile("cp.async.cg.shared.global [%0], [%1], 16;" :: "r"(saddr), "l"(g));
}
__device__ __forceinline__ void cp_commit() {
    asm volatile("cp.async.commit_group;" ::: "memory");
}
__device__ __forceinline__ void cp_wait0() {
    asm volatile("cp.async.wait_group 0;" ::: "memory");
}
__device__ __forceinline__ void cp_wait1() {
    asm volatile("cp.async.wait_group 1;" ::: "memory");
}
__device__ __forceinline__ void ldsm4(uint32_t* r, uint32_t saddr) {
    asm volatile("ldmatrix.sync.aligned.m8n8.x4.shared.b16 {%0,%1,%2,%3}, [%4];"
        : "=r"(r[0]), "=r"(r[1]), "=r"(r[2]), "=r"(r[3]) : "r"(saddr));
}
__device__ __forceinline__ void ldsm2(uint32_t* r, uint32_t saddr) {
    asm volatile("ldmatrix.sync.aligned.m8n8.x2.shared.b16 {%0,%1}, [%2];"
        : "=r"(r[0]), "=r"(r[1]) : "r"(saddr));
}
__device__ __forceinline__ void ldsm2t(uint32_t* r, uint32_t saddr) {
    asm volatile("ldmatrix.sync.aligned.m8n8.x2.trans.shared.b16 {%0,%1}, [%2];"
        : "=r"(r[0]), "=r"(r[1]) : "r"(saddr));
}
__device__ __forceinline__ void mma16816(float* c, const uint32_t* a, uint32_t b0, uint32_t b1) {
    asm volatile(
        "mma.sync.aligned.m16n8k16.row.col.f32.f16.f16.f32 "
        "{%0,%1,%2,%3}, {%4,%5,%6,%7}, {%8,%9}, {%0,%1,%2,%3};"
        : "+f"(c[0]), "+f"(c[1]), "+f"(c[2]), "+f"(c[3])
        : "r"(a[0]), "r"(a[1]), "r"(a[2]), "r"(a[3]), "r"(b0), "r"(b1));
}
__device__ __forceinline__ uint32_t pack_h2(float a, float b) {
    __half2 h = __floats2half2_rn(a, b);
    return *(uint32_t*)&h;
}
__device__ __forceinline__ uint32_t sw_off(int row, int chunk) {
    return (uint32_t)(row * 64 + ((chunk ^ ((row >> 1) & 3)) << 4));
}
__device__ __forceinline__ float silu_mul(float a, float b) {
    return a * (1.f / (1.f + __expf(-a))) * b;
}

// ---------------- HMMA GEMM: C[M,N] = A[M,K](fp16)*B[N,K](fp16)^T (+resid) ----------------
#define BM 128
#define BN 128
#define BK 32
#define TILE_B 8192

template<bool OUT_HALF>
__global__ void __launch_bounds__(256) gemm_hmma(
    const __half* __restrict__ A, const __half* __restrict__ B,
    const float* __restrict__ resid, void* __restrict__ Cv,
    int M, int N, int K)
{
    __shared__ __align__(128) __half As[2][BM*BK];
    __shared__ __align__(128) __half Bs[2][BN*BK];

    int tid = threadIdx.x;
    int wid = tid >> 5, lane = tid & 31;
    int wm = wid & 3, wn = wid >> 2;
    int m0 = blockIdx.y * BM, n0 = blockIdx.x * BN;

    uint32_t as_base = smem_u32(As);
    uint32_t bs_base = smem_u32(Bs);

    int lr = tid >> 1;
    int lc = (tid & 1) * 2;
    const char* gA = (const char*)(A + (size_t)(m0 + lr) * K) + lc * 16;
    const char* gB = (const char*)(B + (size_t)(n0 + lr) * K) + lc * 16;
    uint32_t sA0 = as_base + sw_off(lr, lc);
    uint32_t sA1 = as_base + sw_off(lr, lc + 1);
    uint32_t sB0 = bs_base + sw_off(lr, lc);
    uint32_t sB1 = bs_base + sw_off(lr, lc + 1);

    int rowsel = ((lane >> 3) & 1) * 8 + (lane & 7);
    int chunk_hi = lane >> 4;

    float acc[2][8][4];
    #pragma unroll
    for (int mt = 0; mt < 2; mt++)
        #pragma unroll
        for (int nt = 0; nt < 8; nt++)
            #pragma unroll
            for (int i = 0; i < 4; i++) acc[mt][nt][i] = 0.f;

    int iters = K / BK;
    cp16(sA0, gA); cp16(sA1, gA + 16);
    cp16(sB0, gB); cp16(sB1, gB + 16);
    cp_commit();
    cp_wait0();
    __syncthreads();

    int buf = 0;
    for (int kb = 0; kb < iters; kb++) {
        if (kb + 1 < iters) {
            size_t go = (size_t)(kb + 1) * (BK * 2);
            uint32_t bo = (buf ^ 1) * TILE_B;
            cp16(sA0 + bo, gA + go); cp16(sA1 + bo, gA + go + 16);
            cp16(sB0 + bo, gB + go); cp16(sB1 + bo, gB + go + 16);
            cp_commit();
        }
        uint32_t ab = as_base + buf * TILE_B;
        uint32_t bb = bs_base + buf * TILE_B;
        #pragma unroll
        for (int ks = 0; ks < 2; ks++) {
            int cb = ks * 2 + chunk_hi;
            uint32_t a[2][4];
            #pragma unroll
            for (int mt = 0; mt < 2; mt++) {
                int row = wm * 32 + mt * 16 + rowsel;
                ldsm4(a[mt], ab + sw_off(row, cb));
            }
            uint32_t b[4][4];
            #pragma unroll
            for (int p = 0; p < 4; p++) {
                int row = wn * 64 + p * 16 + rowsel;
                ldsm4(b[p], bb + sw_off(row, cb));
            }
            #pragma unroll
            for (int mt = 0; mt < 2; mt++)
                #pragma unroll
                for (int nt = 0; nt < 8; nt++) {
                    int p = nt >> 1, q = nt & 1;
                    mma16816(acc[mt][nt], a[mt], b[p][q], b[p][2 + q]);
                }
        }
        if (kb + 1 < iters) cp_wait0();
        __syncthreads();
        buf ^= 1;
    }

    int r0 = lane >> 2, c0 = (lane & 3) * 2;
    #pragma unroll
    for (int mt = 0; mt < 2; mt++) {
        #pragma unroll
        for (int nt = 0; nt < 8; nt++) {
            int row = m0 + wm * 32 + mt * 16 + r0;
            int col = n0 + wn * 64 + nt * 8 + c0;
            if (OUT_HALF) {
                __half* C = (__half*)Cv;
                *(uint32_t*)(C + (size_t)row * N + col)       = pack_h2(acc[mt][nt][0], acc[mt][nt][1]);
                *(uint32_t*)(C + (size_t)(row + 8) * N + col) = pack_h2(acc[mt][nt][2], acc[mt][nt][3]);
            } else {
                float* C = (float*)Cv;
                float2 v0 = make_float2(acc[mt][nt][0], acc[mt][nt][1]);
                float2 v1 = make_float2(acc[mt][nt][2], acc[mt][nt][3]);
                if (resid) {
                    float2 a0 = *(const float2*)(resid + (size_t)row * N + col);
                    float2 a1 = *(const float2*)(resid + (size_t)(row + 8) * N + col);
                    v0.x += a0.x; v0.y += a0.y; v1.x += a1.x; v1.y += a1.y;
                }
                *(float2*)(C + (size_t)row * N + col)       = v0;
                *(float2*)(C + (size_t)(row + 8) * N + col) = v1;
            }
        }
    }
}

// ---------------- Fused FFN-up: H = silu(A*W1^T) * (A*W3^T), fp16 out ----------------
// Same tiling as gemm_hmma; A smem tile shared between the two weight GEMMs.
__global__ void __launch_bounds__(256) gemm_ffup(
    const __half* __restrict__ A, const __half* __restrict__ B1,
    const __half* __restrict__ B2, __half* __restrict__ H,
    int M, int N, int K)
{
    __shared__ __align__(128) __half As [2][BM*BK];
    __shared__ __align__(128) __half B1s[2][BN*BK];
    __shared__ __align__(128) __half B2s[2][BN*BK];

    int tid = threadIdx.x;
    int wid = tid >> 5, lane = tid & 31;
    int wm = wid & 3, wn = wid >> 2;
    int m0 = blockIdx.y * BM, n0 = blockIdx.x * BN;

    uint32_t as_base  = smem_u32(As);
    uint32_t b1_base  = smem_u32(B1s);
    uint32_t b2_base  = smem_u32(B2s);

    int lr = tid >> 1;
    int lc = (tid & 1) * 2;
    const char* gA  = (const char*)(A  + (size_t)(m0 + lr) * K) + lc * 16;
    const char* gB1 = (const char*)(B1 + (size_t)(n0 + lr) * K) + lc * 16;
    const char* gB2 = (const char*)(B2 + (size_t)(n0 + lr) * K) + lc * 16;
    uint32_t so0 = sw_off(lr, lc), so1 = sw_off(lr, lc + 1);

    int rowsel = ((lane >> 3) & 1) * 8 + (lane & 7);
    int chunk_hi = lane >> 4;

    float acc1[2][8][4], acc2[2][8][4];
    #pragma unroll
    for (int mt = 0; mt < 2; mt++)
        #pragma unroll
        for (int nt = 0; nt < 8; nt++)
            #pragma unroll
            for (int i = 0; i < 4; i++) { acc1[mt][nt][i] = 0.f; acc2[mt][nt][i] = 0.f; }

    int iters = K / BK;
    cp16(as_base + so0, gA);  cp16(as_base + so1, gA + 16);
    cp16(b1_base + so0, gB1); cp16(b1_base + so1, gB1 + 16);
    cp16(b2_base + so0, gB2); cp16(b2_base + so1, gB2 + 16);
    cp_commit();
    cp_wait0();
    __syncthreads();

    int buf = 0;
    for (int kb = 0; kb < iters; kb++) {
        if (kb + 1 < iters) {
            size_t go = (size_t)(kb + 1) * (BK * 2);
            uint32_t bo = (buf ^ 1) * TILE_B;
            cp16(as_base + bo + so0, gA + go);  cp16(as_base + bo + so1, gA + go + 16);
            cp16(b1_base + bo + so0, gB1 + go); cp16(b1_base + bo + so1, gB1 + go + 16);
            cp16(b2_base + bo + so0, gB2 + go); cp16(b2_base + bo + so1, gB2 + go + 16);
            cp_commit();
        }
        uint32_t ab = as_base + buf * TILE_B;
        uint32_t b1b = b1_base + buf * TILE_B;
        uint32_t b2b = b2_base + buf * TILE_B;
        #pragma unroll
        for (int ks = 0; ks < 2; ks++) {
            int cb = ks * 2 + chunk_hi;
            uint32_t a[2][4];
            #pragma unroll
            for (int mt = 0; mt < 2; mt++) {
                int row = wm * 32 + mt * 16 + rowsel;
                ldsm4(a[mt], ab + sw_off(row, cb));
            }
            #pragma unroll
            for (int p = 0; p < 4; p++) {
                int row = wn * 64 + p * 16 + rowsel;
                uint32_t b1[4], b2[4];
                ldsm4(b1, b1b + sw_off(row, cb));
                ldsm4(b2, b2b + sw_off(row, cb));
                #pragma unroll
                for (int mt = 0; mt < 2; mt++)
                    #pragma unroll
                    for (int q = 0; q < 2; q++) {
                        mma16816(acc1[mt][p*2+q], a[mt], b1[q], b1[2 + q]);
                        mma16816(acc2[mt][p*2+q], a[mt], b2[q], b2[2 + q]);
                    }
            }
        }
        if (kb + 1 < iters) cp_wait0();
        __syncthreads();
        buf ^= 1;
    }

    int r0 = lane >> 2, c0 = (lane & 3) * 2;
    #pragma unroll
    for (int mt = 0; mt < 2; mt++) {
        #pragma unroll
        for (int nt = 0; nt < 8; nt++) {
            int row = m0 + wm * 32 + mt * 16 + r0;
            int col = n0 + wn * 64 + nt * 8 + c0;
            float h0 = silu_mul(acc1[mt][nt][0], acc2[mt][nt][0]);
            float h1 = silu_mul(acc1[mt][nt][1], acc2[mt][nt][1]);
            float h2 = silu_mul(acc1[mt][nt][2], acc2[mt][nt][2]);
            float h3 = silu_mul(acc1[mt][nt][3], acc2[mt][nt][3]);
            *(uint32_t*)(H + (size_t)row * N + col)       = pack_h2(h0, h1);
            *(uint32_t*)(H + (size_t)(row + 8) * N + col) = pack_h2(h2, h3);
        }
    }
}

// ---------------- HMMA flash attention (fp16 in/out, fp32 softmax) ----------------
__global__ void __launch_bounds__(256) attn_hmma(const __half* __restrict__ qkv,
                                                 __half* __restrict__ out) {
    __shared__ __align__(128) __half Qs[128*64];
    __shared__ __align__(128) __half Ks[2][64*64];
    __shared__ __align__(128) __half Vs[2][64*64];
    const int tid = threadIdx.x, lane = tid & 31, wid = tid >> 5;
    const int b = blockIdx.y >> 4, h = blockIdx.y & 15;
    const int q0 = blockIdx.x * 128;
    const __half* base = qkv + (size_t)b * SEQL * (3*D_MODEL) + h * 64;

    uint32_t qs  = smem_u32(Qs);
    uint32_t ksm = smem_u32(Ks);
    uint32_t vsm = smem_u32(Vs);

    {
        int r = tid >> 1, c0 = (tid & 1) * 4;
        const char* g = (const char*)(base + (size_t)(q0 + r) * (3*D_MODEL));
        #pragma unroll
        for (int c = 0; c < 4; c++) {
            int ch = c0 + c;
            cp16(qs + r * 128 + ((ch ^ (r & 7)) << 4), g + ch * 16);
        }
    }
    const int T = q0 / 64 + 2;

    {
        int r = tid >> 2, c0 = (tid & 3) * 2;
        const char* gk = (const char*)(base + 1024 + (size_t)r * (3*D_MODEL));
        const char* gv = (const char*)(base + 2048 + (size_t)r * (3*D_MODEL));
        #pragma unroll
        for (int c = 0; c < 2; c++) {
            int ch = c0 + c;
            uint32_t sw = r * 128 + ((ch ^ (r & 7)) << 4);
            cp16(ksm + sw, gk + ch * 16);
            cp16(vsm + sw, gv + ch * 16);
        }
    }
    cp_commit();
    cp_wait0();
    __syncthreads();

    uint32_t aq[4][4];
    {
        int row = wid * 16 + (lane & 15);
        #pragma unroll
        for (int ks = 0; ks < 4; ks++) {
            int ch = 2 * ks + (lane >> 4);
            ldsm4(aq[ks], qs + row * 128 + ((ch ^ (row & 7)) << 4));
        }
    }

    float acc_o[8][4];
    #pragma unroll
    for (int j = 0; j < 8; j++)
        #pragma unroll
        for (int i = 0; i < 4; i++) acc_o[j][i] = 0.f;
    float m_lo = -1e30f, m_hi = -1e30f, l_lo = 0.f, l_hi = 0.f;

    for (int t = 0; t < T; t++) {
        int buf = t & 1;
        if (t + 1 < T) {
            int r = tid >> 2, c0 = (tid & 3) * 2;
            const char* gk = (const char*)(base + 1024 + (size_t)((t+1)*64 + r) * (3*D_MODEL));
            const char* gv = (const char*)(base + 2048 + (size_t)((t+1)*64 + r) * (3*D_MODEL));
            uint32_t so = (uint32_t)(buf ^ 1) * 8192 + r * 128;
            #pragma unroll
            for (int c = 0; c < 2; c++) {
                int ch = c0 + c;
                uint32_t sw = so + ((ch ^ (r & 7)) << 4);
                cp16(ksm + sw, gk + ch * 16);
                cp16(vsm + sw, gv + ch * 16);
            }
            cp_commit();
            cp_wait1();
        } else {
            cp_wait0();
        }
        __syncthreads();

        uint32_t kb = ksm + buf * 8192;
        uint32_t vb = vsm + buf * 8192;

        float s[8][4];
        #pragma unroll
        for (int j = 0; j < 8; j++)
            #pragma unroll
            for (int i = 0; i < 4; i++) s[j][i] = 0.f;
        #pragma unroll
        for (int ks = 0; ks < 4; ks++) {
            #pragma unroll
            for (int j = 0; j < 8; j++) {
                int row = j * 8 + (lane & 7);
                int ch = 2 * ks + ((lane >> 3) & 1);
                uint32_t bk[2];
                ldsm2(bk, kb + row * 128 + ((ch ^ (row & 7)) << 4));
                mma16816(s[j], aq[ks], bk[0], bk[1]);
            }
        }

        bool need_mask = (t >= T - 2);
        int q_lo = q0 + wid * 16 + (lane >> 2);
        int kvb  = t * 64 + (lane & 3) * 2;
        float mx_lo = -1e30f, mx_hi = -1e30f;
        #pragma unroll
        for (int j = 0; j < 8; j++) {
            #pragma unroll
            for (int c = 0; c < 4; c++) {
                float v = s[j][c] * 0.125f;
                if (need_mask) {
                    int kv = kvb + j * 8 + (c & 1);
                    int qr = q_lo + ((c >= 2) ? 8 : 0);
                    if (kv > qr) v = -1e30f;
                }
                s[j][c] = v;
            }
            mx_lo = fmaxf(mx_lo, fmaxf(s[j][0], s[j][1]));
            mx_hi = fmaxf(mx_hi, fmaxf(s[j][2], s[j][3]));
        }
        mx_lo = fmaxf(mx_lo, __shfl_xor_sync(0xffffffffu, mx_lo, 1));
        mx_lo = fmaxf(mx_lo, __shfl_xor_sync(0xffffffffu, mx_lo, 2));
        mx_hi = fmaxf(mx_hi, __shfl_xor_sync(0xffffffffu, mx_hi, 1));
        mx_hi = fmaxf(mx_hi, __shfl_xor_sync(0xffffffffu, mx_hi, 2));

        float mn_lo = fmaxf(m_lo, mx_lo), mn_hi = fmaxf(m_hi, mx_hi);
        float cr_lo = __expf(m_lo - mn_lo), cr_hi = __expf(m_hi - mn_hi);
        m_lo = mn_lo; m_hi = mn_hi;

        float pl = 0.f, ph = 0.f;
        #pragma unroll
        for (int j = 0; j < 8; j++) {
            s[j][0] = __expf(s[j][0] - mn_lo); pl += s[j][0];
            s[j][1] = __expf(s[j][1] - mn_lo); pl += s[j][1];
            s[j][2] = __expf(s[j][2] - mn_hi); ph += s[j][2];
            s[j][3] = __expf(s[j][3] - mn_hi); ph += s[j][3];
        }
        pl += __shfl_xor_sync(0xffffffffu, pl, 1);
        pl += __shfl_xor_sync(0xffffffffu, pl, 2);
        ph += __shfl_xor_sync(0xffffffffu, ph, 1);
        ph += __shfl_xor_sync(0xffffffffu, ph, 2);
        l_lo = l_lo * cr_lo + pl;
        l_hi = l_hi * cr_hi + ph;

        #pragma unroll
        for (int j = 0; j < 8; j++) {
            acc_o[j][0] *= cr_lo; acc_o[j][1] *= cr_lo;
            acc_o[j][2] *= cr_hi; acc_o[j][3] *= cr_hi;
        }

        uint32_t ap[4][4];
        #pragma unroll
        for (int c16 = 0; c16 < 4; c16++) {
            ap[c16][0] = pack_h2(s[2*c16][0],   s[2*c16][1]);
            ap[c16][1] = pack_h2(s[2*c16][2],   s[2*c16][3]);
            ap[c16][2] = pack_h2(s[2*c16+1][0], s[2*c16+1][1]);
            ap[c16][3] = pack_h2(s[2*c16+1][2], s[2*c16+1][3]);
        }

        #pragma unroll
        for (int c16 = 0; c16 < 4; c16++) {
            int row = c16 * 16 + (lane & 15);
            #pragma unroll
            for (int j = 0; j < 8; j++) {
                uint32_t bv[2];
                ldsm2t(bv, vb + row * 128 + ((j ^ (row & 7)) << 4));
                mma16816(acc_o[j], ap[c16], bv[0], bv[1]);
            }
        }
        __syncthreads();
    }

    float il_lo = 1.f / l_lo, il_hi = 1.f / l_hi;
    int r = lane >> 2, c = (lane & 3) * 2;
    __half* o_lo = out + (size_t)((b*SEQL) + q0 + wid*16 + r) * D_MODEL + h * 64 + c;
    __half* o_hi = o_lo + (size_t)8 * D_MODEL;
    #pragma unroll
    for (int j = 0; j < 8; j++) {
        *(uint32_t*)(o_lo + j*8) = pack_h2(acc_o[j][0]*il_lo, acc_o[j][1]*il_lo);
        *(uint32_t*)(o_hi + j*8) = pack_h2(acc_o[j][2]*il_hi, acc_o[j][3]*il_hi);
    }
}

// ---------------- fp32 -> fp16 convert ----------------
__global__ void f2h_k(const float* __restrict__ x, __half* __restrict__ y, int n4) {
    int i = blockIdx.x * blockDim.x + threadIdx.x;
    if (i < n4) {
        float4 v = ((const float4*)x)[i];
        ((uint2*)y)[i] = make_uint2(pack_h2(v.x, v.y), pack_h2(v.z, v.w));
    }
}

// ---------------- RMSNorm -> fp16 ----------------
__global__ void rmsnorm_k(const float* __restrict__ x, const float* __restrict__ g,
                          __half* __restrict__ out) {
    int row = blockIdx.x;
    const float4* x4 = (const float4*)(x + (size_t)row * D_MODEL);
    const float4* g4 = (const float4*)g;
    float4 v = x4[threadIdx.x];
    float ss = v.x*v.x + v.y*v.y + v.z*v.z + v.w*v.w;
    #pragma unroll
    for (int o = 16; o; o >>= 1) ss += __shfl_xor_sync(0xffffffffu, ss, o);
    __shared__ float wsum[8];
    int w = threadIdx.x >> 5, l = threadIdx.x & 31;
    if (l == 0) wsum[w] = ss;
    __syncthreads();
    if (w == 0) {
        float t = (l < 8) ? wsum[l] : 0.f;
        #pragma unroll
        for (int o = 4; o; o >>= 1) t += __shfl_xor_sync(0xffffffffu, t, o);
        if (l == 0) wsum[0] = t;
    }
    __syncthreads();
    float inv = rsqrtf(wsum[0] * (1.0f / (float)D_MODEL) + 1e-5f);
    float4 gg = g4[threadIdx.x];
    ((uint2*)(out + (size_t)row * D_MODEL))[threadIdx.x] =
        make_uint2(pack_h2(v.x*gg.x*inv, v.y*gg.y*inv), pack_h2(v.z*gg.z*inv, v.w*gg.w*inv));
}

// ---------------- launch ----------------
extern "C" void kernel_launch(void* const* d_in, const int* in_sizes, int n_in,
                              void* d_out, int out_size) {
    const float* x    = (const float*)d_in[0];
    const float* wqkv = (const float*)d_in[1];
    const float* wo   = (const float*)d_in[2];
    const float* g1   = (const float*)d_in[3];
    const float* g2   = (const float*)d_in[4];
    const float* w1   = (const float*)d_in[5];
    const float* w2   = (const float*)d_in[6];
    const float* w3   = (const float*)d_in[7];
    float* out = (float*)d_out;

    __half *xnh, *qkvh, *attnh, *ffhh, *wh;
    cudaGetSymbolAddress((void**)&xnh,   g_xnh);
    cudaGetSymbolAddress((void**)&qkvh,  g_qkvh);
    cudaGetSymbolAddress((void**)&attnh, g_attnh);
    cudaGetSymbolAddress((void**)&ffhh,  g_ffhh);
    cudaGetSymbolAddress((void**)&wh,    g_wh);

    size_t o_qkv = 0;
    size_t o_wo  = o_qkv + (size_t)3*D_MODEL*D_MODEL;
    size_t o_w1  = o_wo  + (size_t)D_MODEL*D_MODEL;
    size_t o_w3  = o_w1  + (size_t)DFF*D_MODEL;
    size_t o_w2  = o_w3  + (size_t)DFF*D_MODEL;

    f2h_k<<<(3*D_MODEL*D_MODEL/4 + 255)/256, 256>>>(wqkv, wh + o_qkv, 3*D_MODEL*D_MODEL/4);
    f2h_k<<<(D_MODEL*D_MODEL/4 + 255)/256, 256>>>(wo, wh + o_wo, D_MODEL*D_MODEL/4);
    f2h_k<<<(DFF*D_MODEL/4 + 255)/256, 256>>>(w1, wh + o_w1, DFF*D_MODEL/4);
    f2h_k<<<(DFF*D_MODEL/4 + 255)/256, 256>>>(w3, wh + o_w3, DFF*D_MODEL/4);
    f2h_k<<<(D_MODEL*DFF/4 + 255)/256, 256>>>(w2, wh + o_w2, D_MODEL*DFF/4);

    // x1 = x + WO * attn(QKV of rmsnorm(x,g1))
    rmsnorm_k<<<M_ROWS, 256>>>(x, g1, xnh);
    gemm_hmma<true><<<dim3(3*D_MODEL/BN, M_ROWS/BM), 256>>>(
        xnh, wh + o_qkv, nullptr, qkvh, M_ROWS, 3*D_MODEL, D_MODEL);
    attn_hmma<<<dim3(SEQL/128, BATCH*NH), 256>>>(qkvh, attnh);
    gemm_hmma<false><<<dim3(D_MODEL/BN, M_ROWS/BM), 256>>>(
        attnh, wh + o_wo, x, out, M_ROWS, D_MODEL, D_MODEL);

    // out += W2 * swiglu(rmsnorm(out,g2))
    rmsnorm_k<<<M_ROWS, 256>>>(out, g2, xnh);
    gemm_ffup<<<dim3(DFF/BN, M_ROWS/BM), 256>>>(
        xnh, wh + o_w1, wh + o_w3, ffhh, M_ROWS, DFF, D_MODEL);
    gemm_hmma<false><<<dim3(D_MODEL/BN, M_ROWS/BM), 256>>>(
        ffhh, wh + o_w2, out, out, M_ROWS, D_MODEL, DFF);
}